// round 2
// baseline (speedup 1.0000x reference)
#include <cuda_runtime.h>

#define S 768
#define H 256
#define R 51

// Scratch (allocation-free rule: __device__ globals)
__device__ float g_q[S * H];
__device__ float g_k[S * H];
__device__ float g_QK[S * S];

// ---------------------------------------------------------------------------
// Tiled fp32 GEMM: C[M,N] = A[M,K] @ B[N,K]^T (+ bias), all row-major.
// BM=BN=64, BK=32, 256 threads, 4x4 per thread. M,N div 64; K div 32 assumed.
// ---------------------------------------------------------------------------
__device__ __forceinline__ void gemm_nt_64x64(
    const float* __restrict__ A, const float* __restrict__ B,
    const float* __restrict__ bias, float* __restrict__ C,
    int N, int K)
{
    __shared__ float As[32][65];
    __shared__ float Bs[32][65];

    const int bm = blockIdx.y * 64;
    const int bn = blockIdx.x * 64;
    const int tid = threadIdx.x;
    const int tx = tid & 15;   // col group
    const int ty = tid >> 4;   // row group

    float acc[4][4] = {};

    const int lrow = tid >> 2;          // 0..63
    const int lcol = (tid & 3) * 8;     // 0,8,16,24

    for (int k0 = 0; k0 < K; k0 += 32) {
        // Load A tile 64x32 (transposed into smem)
        {
            const float* src = A + (size_t)(bm + lrow) * K + k0 + lcol;
            float4 v0 = *(const float4*)(src);
            float4 v1 = *(const float4*)(src + 4);
            As[lcol + 0][lrow] = v0.x; As[lcol + 1][lrow] = v0.y;
            As[lcol + 2][lrow] = v0.z; As[lcol + 3][lrow] = v0.w;
            As[lcol + 4][lrow] = v1.x; As[lcol + 5][lrow] = v1.y;
            As[lcol + 6][lrow] = v1.z; As[lcol + 7][lrow] = v1.w;
        }
        // Load B tile 64x32 (transposed into smem)
        {
            const float* src = B + (size_t)(bn + lrow) * K + k0 + lcol;
            float4 v0 = *(const float4*)(src);
            float4 v1 = *(const float4*)(src + 4);
            Bs[lcol + 0][lrow] = v0.x; Bs[lcol + 1][lrow] = v0.y;
            Bs[lcol + 2][lrow] = v0.z; Bs[lcol + 3][lrow] = v0.w;
            Bs[lcol + 4][lrow] = v1.x; Bs[lcol + 5][lrow] = v1.y;
            Bs[lcol + 6][lrow] = v1.z; Bs[lcol + 7][lrow] = v1.w;
        }
        __syncthreads();

        #pragma unroll
        for (int kk = 0; kk < 32; kk++) {
            float a[4], b[4];
            #pragma unroll
            for (int m = 0; m < 4; m++) a[m] = As[kk][ty * 4 + m];
            #pragma unroll
            for (int n = 0; n < 4; n++) b[n] = Bs[kk][tx * 4 + n];
            #pragma unroll
            for (int m = 0; m < 4; m++)
                #pragma unroll
                for (int n = 0; n < 4; n++)
                    acc[m][n] = fmaf(a[m], b[n], acc[m][n]);
        }
        __syncthreads();
    }

    #pragma unroll
    for (int m = 0; m < 4; m++) {
        int row = bm + ty * 4 + m;
        #pragma unroll
        for (int n = 0; n < 4; n++) {
            int col = bn + tx * 4 + n;
            float v = acc[m][n];
            if (bias) v += bias[col];
            C[(size_t)row * N + col] = v;
        }
    }
}

// Projections: z==0 -> q = query@Wq^T+bq ; z==1 -> k = key@Wk^T+bk
__global__ void __launch_bounds__(256) proj_kernel(
    const float* __restrict__ query, const float* __restrict__ key,
    const float* __restrict__ Wq, const float* __restrict__ bq,
    const float* __restrict__ Wk, const float* __restrict__ bk)
{
    if (blockIdx.z == 0) gemm_nt_64x64(query, Wq, bq, g_q, H, H);
    else                 gemm_nt_64x64(key,  Wk, bk, g_k, H, H);
}

// QK^T: g_QK[768,768] = g_q @ g_k^T
__global__ void __launch_bounds__(256) qk_kernel()
{
    gemm_nt_64x64(g_q, g_k, nullptr, g_QK, S, H);
}

// ---------------------------------------------------------------------------
// Fused per-row: T[i,r] = q[i]·rel_k_emb[r], then
// out[i,j] = softmax_j( (QK[i,j] + T[i,rel[i,j]]) / 16, mask )
// One block (256 threads) per row i.
// ---------------------------------------------------------------------------
__global__ void __launch_bounds__(256) softmax_kernel(
    const int* __restrict__ rel, const int* __restrict__ mask,
    const float* __restrict__ rel_k_emb, float* __restrict__ out)
{
    const int i = blockIdx.x;
    const int tid = threadIdx.x;
    const int lane = tid & 31;
    const int warp = tid >> 5;

    __shared__ float qs[H];
    __shared__ float Ts[R];
    __shared__ float red[8];
    __shared__ float bcast;

    qs[tid] = g_q[(size_t)i * H + tid];
    __syncthreads();

    if (tid < R) {
        const float* e = rel_k_emb + (size_t)tid * H;
        float a0 = 0.f, a1 = 0.f, a2 = 0.f, a3 = 0.f;
        #pragma unroll 8
        for (int c = 0; c < H; c += 4) {
            a0 = fmaf(qs[c + 0], e[c + 0], a0);
            a1 = fmaf(qs[c + 1], e[c + 1], a1);
            a2 = fmaf(qs[c + 2], e[c + 2], a2);
            a3 = fmaf(qs[c + 3], e[c + 3], a3);
        }
        Ts[tid] = (a0 + a1) + (a2 + a3);
    }
    __syncthreads();

    // per-thread 3 columns
    float s[3];
    float mx = -1e30f;
    #pragma unroll
    for (int v = 0; v < 3; v++) {
        const int j = tid + v * 256;
        const size_t idx = (size_t)i * S + j;
        const int r = rel[idx];
        float sc = (g_QK[idx] + Ts[r]) * 0.0625f;  // 1/sqrt(256)
        if (mask[idx] == 0) sc = -1e9f;
        s[v] = sc;
        mx = fmaxf(mx, sc);
    }

    // block max
    #pragma unroll
    for (int o = 16; o > 0; o >>= 1) mx = fmaxf(mx, __shfl_xor_sync(0xffffffffu, mx, o));
    if (lane == 0) red[warp] = mx;
    __syncthreads();
    if (warp == 0) {
        float m = red[lane & 7];
        #pragma unroll
        for (int o = 4; o > 0; o >>= 1) m = fmaxf(m, __shfl_xor_sync(0xffffffffu, m, o));
        if (lane == 0) bcast = m;
    }
    __syncthreads();
    mx = bcast;

    float sum = 0.f;
    #pragma unroll
    for (int v = 0; v < 3; v++) {
        s[v] = __expf(s[v] - mx);
        sum += s[v];
    }

    // block sum
    #pragma unroll
    for (int o = 16; o > 0; o >>= 1) sum += __shfl_xor_sync(0xffffffffu, sum, o);
    if (lane == 0) red[warp] = sum;
    __syncthreads();
    if (warp == 0) {
        float m = red[lane & 7];
        #pragma unroll
        for (int o = 4; o > 0; o >>= 1) m += __shfl_xor_sync(0xffffffffu, m, o);
        if (lane == 0) bcast = m;
    }
    __syncthreads();
    const float inv = 1.0f / bcast;

    #pragma unroll
    for (int v = 0; v < 3; v++) {
        out[(size_t)i * S + tid + v * 256] = s[v] * inv;
    }
}

extern "C" void kernel_launch(void* const* d_in, const int* in_sizes, int n_in,
                              void* d_out, int out_size)
{
    // metadata order: query, key, value, relation, mask, Wq, bq, Wk, bk, Wv, bv,
    //                 rel_k_emb, rel_v_emb
    const float* query = (const float*)d_in[0];
    const float* key   = (const float*)d_in[1];
    const int*   rel   = (const int*)d_in[3];   // int32 (JAX x64 disabled)
    const int*   mask  = (const int*)d_in[4];
    const float* Wq    = (const float*)d_in[5];
    const float* bq    = (const float*)d_in[6];
    const float* Wk    = (const float*)d_in[7];
    const float* bk    = (const float*)d_in[8];
    const float* rke   = (const float*)d_in[11];
    float*       out   = (float*)d_out;

    dim3 gproj(H / 64, S / 64, 2);   // (4, 12, 2)
    proj_kernel<<<gproj, 256>>>(query, key, Wq, bq, Wk, bk);

    dim3 gqk(S / 64, S / 64, 1);     // (12, 12)
    qk_kernel<<<gqk, 256>>>();

    softmax_kernel<<<S, 256>>>(rel, mask, rke, out);
}

// round 3
// speedup vs baseline: 1.0191x; 1.0191x over previous
#include <cuda_runtime.h>

#define S 768
#define H 256
#define R 51

// Scratch (allocation-free rule: __device__ globals)
__device__ float g_q[S * H];
__device__ float g_k[S * H];
__device__ float g_QK[S * S];

// ---------------------------------------------------------------------------
// Tiled fp32 GEMM: C[M,N] = A[M,K] @ B[N,K]^T (+ bias), all row-major.
// BM=BN=64, BK=32, 256 threads, 4x4 per thread.
// Double-buffered smem + register prefetch, float4 LDS frag reads.
// N, K compile-time.
// ---------------------------------------------------------------------------
template<int N, int K>
__device__ __forceinline__ void gemm_nt_64x64(
    const float* __restrict__ A, const float* __restrict__ B,
    const float* __restrict__ bias, float* __restrict__ C)
{
    // pad 68 floats (272B, multiple of 16B) so rows are float4-aligned
    __shared__ __align__(16) float As[2][32][68];
    __shared__ __align__(16) float Bs[2][32][68];

    const int bm = blockIdx.y * 64;
    const int bn = blockIdx.x * 64;
    const int tid = threadIdx.x;
    const int tx = tid & 15;   // col group (0..15)
    const int ty = tid >> 4;   // row group (0..15)

    const int lrow = tid >> 2;          // 0..63
    const int lcol = (tid & 3) * 8;     // 0,8,16,24

    const float* pA = A + (size_t)(bm + lrow) * K + lcol;
    const float* pB = B + (size_t)(bn + lrow) * K + lcol;

    float acc[4][4] = {};

    // --- prologue: load tile 0 ---
    float4 a0 = *(const float4*)(pA);
    float4 a1 = *(const float4*)(pA + 4);
    float4 b0 = *(const float4*)(pB);
    float4 b1 = *(const float4*)(pB + 4);
    {
        As[0][lcol + 0][lrow] = a0.x; As[0][lcol + 1][lrow] = a0.y;
        As[0][lcol + 2][lrow] = a0.z; As[0][lcol + 3][lrow] = a0.w;
        As[0][lcol + 4][lrow] = a1.x; As[0][lcol + 5][lrow] = a1.y;
        As[0][lcol + 6][lrow] = a1.z; As[0][lcol + 7][lrow] = a1.w;
        Bs[0][lcol + 0][lrow] = b0.x; Bs[0][lcol + 1][lrow] = b0.y;
        Bs[0][lcol + 2][lrow] = b0.z; Bs[0][lcol + 3][lrow] = b0.w;
        Bs[0][lcol + 4][lrow] = b1.x; Bs[0][lcol + 5][lrow] = b1.y;
        Bs[0][lcol + 6][lrow] = b1.z; Bs[0][lcol + 7][lrow] = b1.w;
    }
    __syncthreads();

    constexpr int NT = K / 32;
    #pragma unroll
    for (int t = 0; t < NT; t++) {
        const int cur = t & 1;
        // prefetch next tile into registers (latency hidden by compute below)
        if (t + 1 < NT) {
            const float* qA = pA + (t + 1) * 32;
            const float* qB = pB + (t + 1) * 32;
            a0 = *(const float4*)(qA);
            a1 = *(const float4*)(qA + 4);
            b0 = *(const float4*)(qB);
            b1 = *(const float4*)(qB + 4);
        }

        #pragma unroll
        for (int kk = 0; kk < 32; kk++) {
            float4 av = *(const float4*)&As[cur][kk][ty * 4];
            float4 bv = *(const float4*)&Bs[cur][kk][tx * 4];
            acc[0][0] = fmaf(av.x, bv.x, acc[0][0]);
            acc[0][1] = fmaf(av.x, bv.y, acc[0][1]);
            acc[0][2] = fmaf(av.x, bv.z, acc[0][2]);
            acc[0][3] = fmaf(av.x, bv.w, acc[0][3]);
            acc[1][0] = fmaf(av.y, bv.x, acc[1][0]);
            acc[1][1] = fmaf(av.y, bv.y, acc[1][1]);
            acc[1][2] = fmaf(av.y, bv.z, acc[1][2]);
            acc[1][3] = fmaf(av.y, bv.w, acc[1][3]);
            acc[2][0] = fmaf(av.z, bv.x, acc[2][0]);
            acc[2][1] = fmaf(av.z, bv.y, acc[2][1]);
            acc[2][2] = fmaf(av.z, bv.z, acc[2][2]);
            acc[2][3] = fmaf(av.z, bv.w, acc[2][3]);
            acc[3][0] = fmaf(av.w, bv.x, acc[3][0]);
            acc[3][1] = fmaf(av.w, bv.y, acc[3][1]);
            acc[3][2] = fmaf(av.w, bv.z, acc[3][2]);
            acc[3][3] = fmaf(av.w, bv.w, acc[3][3]);
        }

        if (t + 1 < NT) {
            const int nxt = cur ^ 1;
            As[nxt][lcol + 0][lrow] = a0.x; As[nxt][lcol + 1][lrow] = a0.y;
            As[nxt][lcol + 2][lrow] = a0.z; As[nxt][lcol + 3][lrow] = a0.w;
            As[nxt][lcol + 4][lrow] = a1.x; As[nxt][lcol + 5][lrow] = a1.y;
            As[nxt][lcol + 6][lrow] = a1.z; As[nxt][lcol + 7][lrow] = a1.w;
            Bs[nxt][lcol + 0][lrow] = b0.x; Bs[nxt][lcol + 1][lrow] = b0.y;
            Bs[nxt][lcol + 2][lrow] = b0.z; Bs[nxt][lcol + 3][lrow] = b0.w;
            Bs[nxt][lcol + 4][lrow] = b1.x; Bs[nxt][lcol + 5][lrow] = b1.y;
            Bs[nxt][lcol + 6][lrow] = b1.z; Bs[nxt][lcol + 7][lrow] = b1.w;
        }
        __syncthreads();
    }

    // epilogue: float4 stores
    #pragma unroll
    for (int m = 0; m < 4; m++) {
        const int row = bm + ty * 4 + m;
        const int col = bn + tx * 4;
        float4 v = make_float4(acc[m][0], acc[m][1], acc[m][2], acc[m][3]);
        if (bias) {
            v.x += bias[col + 0]; v.y += bias[col + 1];
            v.z += bias[col + 2]; v.w += bias[col + 3];
        }
        *(float4*)&C[(size_t)row * N + col] = v;
    }
}

// Projections: z==0 -> q = query@Wq^T+bq ; z==1 -> k = key@Wk^T+bk
__global__ void __launch_bounds__(256) proj_kernel(
    const float* __restrict__ query, const float* __restrict__ key,
    const float* __restrict__ Wq, const float* __restrict__ bq,
    const float* __restrict__ Wk, const float* __restrict__ bk)
{
    if (blockIdx.z == 0) gemm_nt_64x64<H, H>(query, Wq, bq, g_q);
    else                 gemm_nt_64x64<H, H>(key,  Wk, bk, g_k);
}

// QK^T: g_QK[768,768] = g_q @ g_k^T
__global__ void __launch_bounds__(256) qk_kernel()
{
    gemm_nt_64x64<S, H>(g_q, g_k, nullptr, g_QK);
}

// ---------------------------------------------------------------------------
// Fused per-row: T[i,r] = q[i]·rel_k_emb[r], then
// out[i,j] = softmax_j( (QK[i,j] + T[i,rel[i,j]]) / 16, mask )
// One block (256 threads) per row i.
// ---------------------------------------------------------------------------
__global__ void __launch_bounds__(256) softmax_kernel(
    const int* __restrict__ rel, const int* __restrict__ mask,
    const float* __restrict__ rel_k_emb, float* __restrict__ out)
{
    const int i = blockIdx.x;
    const int tid = threadIdx.x;
    const int lane = tid & 31;
    const int warp = tid >> 5;

    __shared__ float qs[H];
    __shared__ float Tpart[4][R];
    __shared__ float Ts[R];
    __shared__ float red[8];
    __shared__ float bcast;

    qs[tid] = g_q[(size_t)i * H + tid];
    __syncthreads();

    // T[r] = q[i] . rel_k_emb[r], 4-way split over H (64 elems per partial)
    {
        const int r = tid & 63;
        const int sub = tid >> 6;   // 0..3
        if (r < R) {
            const float* e = rel_k_emb + (size_t)r * H + sub * 64;
            const float* qq = qs + sub * 64;
            float s0 = 0.f, s1 = 0.f, s2 = 0.f, s3 = 0.f;
            #pragma unroll
            for (int c = 0; c < 64; c += 4) {
                s0 = fmaf(qq[c + 0], e[c + 0], s0);
                s1 = fmaf(qq[c + 1], e[c + 1], s1);
                s2 = fmaf(qq[c + 2], e[c + 2], s2);
                s3 = fmaf(qq[c + 3], e[c + 3], s3);
            }
            Tpart[sub][r] = (s0 + s1) + (s2 + s3);
        }
    }
    __syncthreads();
    if (tid < R)
        Ts[tid] = (Tpart[0][tid] + Tpart[1][tid]) + (Tpart[2][tid] + Tpart[3][tid]);
    __syncthreads();

    // per-thread 3 columns
    float s[3];
    float mx = -1e30f;
    #pragma unroll
    for (int v = 0; v < 3; v++) {
        const int j = tid + v * 256;
        const size_t idx = (size_t)i * S + j;
        const int r = rel[idx];
        float sc = (g_QK[idx] + Ts[r]) * 0.0625f;  // 1/sqrt(256)
        if (mask[idx] == 0) sc = -1e9f;
        s[v] = sc;
        mx = fmaxf(mx, sc);
    }

    // block max
    #pragma unroll
    for (int o = 16; o > 0; o >>= 1) mx = fmaxf(mx, __shfl_xor_sync(0xffffffffu, mx, o));
    if (lane == 0) red[warp] = mx;
    __syncthreads();
    if (warp == 0) {
        float m = red[lane & 7];
        #pragma unroll
        for (int o = 4; o > 0; o >>= 1) m = fmaxf(m, __shfl_xor_sync(0xffffffffu, m, o));
        if (lane == 0) bcast = m;
    }
    __syncthreads();
    mx = bcast;

    float sum = 0.f;
    #pragma unroll
    for (int v = 0; v < 3; v++) {
        s[v] = __expf(s[v] - mx);
        sum += s[v];
    }

    // block sum
    #pragma unroll
    for (int o = 16; o > 0; o >>= 1) sum += __shfl_xor_sync(0xffffffffu, sum, o);
    if (lane == 0) red[warp] = sum;
    __syncthreads();
    if (warp == 0) {
        float m = red[lane & 7];
        #pragma unroll
        for (int o = 4; o > 0; o >>= 1) m += __shfl_xor_sync(0xffffffffu, m, o);
        if (lane == 0) bcast = m;
    }
    __syncthreads();
    const float inv = 1.0f / bcast;

    #pragma unroll
    for (int v = 0; v < 3; v++) {
        out[(size_t)i * S + tid + v * 256] = s[v] * inv;
    }
}

extern "C" void kernel_launch(void* const* d_in, const int* in_sizes, int n_in,
                              void* d_out, int out_size)
{
    // metadata order: query, key, value, relation, mask, Wq, bq, Wk, bk, Wv, bv,
    //                 rel_k_emb, rel_v_emb
    const float* query = (const float*)d_in[0];
    const float* key   = (const float*)d_in[1];
    const int*   rel   = (const int*)d_in[3];   // int32 (JAX x64 disabled)
    const int*   mask  = (const int*)d_in[4];
    const float* Wq    = (const float*)d_in[5];
    const float* bq    = (const float*)d_in[6];
    const float* Wk    = (const float*)d_in[7];
    const float* bk    = (const float*)d_in[8];
    const float* rke   = (const float*)d_in[11];
    float*       out   = (float*)d_out;

    dim3 gproj(H / 64, S / 64, 2);   // (4, 12, 2)
    proj_kernel<<<gproj, 256>>>(query, key, Wq, bq, Wk, bk);

    dim3 gqk(S / 64, S / 64, 1);     // (12, 12)
    qk_kernel<<<gqk, 256>>>();

    softmax_kernel<<<S, 256>>>(rel, mask, rke, out);
}

// round 5
// speedup vs baseline: 2.0940x; 2.0548x over previous
#include <cuda_runtime.h>

#define S 768
#define H 256
#define R 51
#define TPAD 64   // padded relation-kind count for g_T

// Scratch (allocation-free rule: __device__ globals)
__device__ float g_q[S * H];
__device__ float g_k[S * H];
__device__ float g_QK[S * S];
__device__ float g_T[S * TPAD];

struct SmemTiles {
    float As[2][32][64];
    float Bs[2][32][64];
};

// ---------------------------------------------------------------------------
// Tiled fp32 GEMM: C[bm:bm+64, bn:bn+64] = A[64,K] @ B[64,K]^T (+ bias).
// 256 threads, 4x4 per thread, double-buffered XOR-swizzled smem.
// Swizzle: element (k, col) stored at [k][col ^ (k & 24)] -> conflict-free
// scalar STS (transpose store) AND conflict-free float4 LDS frag reads.
// b_row_max clamps B row index (for padded-N GEMMs reading a short B).
// Smem passed in by the kernel so multiple instantiations share one block.
// ---------------------------------------------------------------------------
template<int N, int K>
__device__ __forceinline__ void gemm_nt_64x64(
    SmemTiles& sm,
    const float* __restrict__ A, const float* __restrict__ B,
    const float* __restrict__ bias, float* __restrict__ C,
    int bm, int bn, int b_row_max)
{
    const int tid = threadIdx.x;
    const int tx = tid & 15;   // col group (0..15)
    const int ty = tid >> 4;   // row group (0..15)

    const int lrow = tid >> 2;          // 0..63
    const int lcol = (tid & 3) * 8;     // 0,8,16,24  (k-offset of 8-float chunk)

    int arow = bm + lrow;
    int brow = bn + lrow; if (brow > b_row_max) brow = b_row_max;
    const float* pA = A + (size_t)arow * K + lcol;
    const float* pB = B + (size_t)brow * K + lcol;

    // swizzled store column: col' = lrow ^ ((lcol+c) & 24) = lrow ^ lcol
    const int scol = lrow ^ lcol;

    float acc[4][4] = {};
    float4 a0, a1, b0, b1;

    // prologue: tile 0
    a0 = *(const float4*)(pA);     a1 = *(const float4*)(pA + 4);
    b0 = *(const float4*)(pB);     b1 = *(const float4*)(pB + 4);
    {
        sm.As[0][lcol + 0][scol] = a0.x; sm.As[0][lcol + 1][scol] = a0.y;
        sm.As[0][lcol + 2][scol] = a0.z; sm.As[0][lcol + 3][scol] = a0.w;
        sm.As[0][lcol + 4][scol] = a1.x; sm.As[0][lcol + 5][scol] = a1.y;
        sm.As[0][lcol + 6][scol] = a1.z; sm.As[0][lcol + 7][scol] = a1.w;
        sm.Bs[0][lcol + 0][scol] = b0.x; sm.Bs[0][lcol + 1][scol] = b0.y;
        sm.Bs[0][lcol + 2][scol] = b0.z; sm.Bs[0][lcol + 3][scol] = b0.w;
        sm.Bs[0][lcol + 4][scol] = b1.x; sm.Bs[0][lcol + 5][scol] = b1.y;
        sm.Bs[0][lcol + 6][scol] = b1.z; sm.Bs[0][lcol + 7][scol] = b1.w;
    }
    __syncthreads();

    constexpr int NT = K / 32;
    #pragma unroll 1
    for (int t = 0; t < NT; t++) {
        const int cur = t & 1;
        // prefetch next tile into registers
        if (t + 1 < NT) {
            const float* qA = pA + (t + 1) * 32;
            const float* qB = pB + (t + 1) * 32;
            a0 = *(const float4*)(qA); a1 = *(const float4*)(qA + 4);
            b0 = *(const float4*)(qB); b1 = *(const float4*)(qB + 4);
        }

        #pragma unroll 16
        for (int kk = 0; kk < 32; kk++) {
            const int sw = kk & 24;
            float4 av = *(const float4*)&sm.As[cur][kk][(ty * 4) ^ sw];
            float4 bv = *(const float4*)&sm.Bs[cur][kk][(tx * 4) ^ sw];
            acc[0][0] = fmaf(av.x, bv.x, acc[0][0]);
            acc[0][1] = fmaf(av.x, bv.y, acc[0][1]);
            acc[0][2] = fmaf(av.x, bv.z, acc[0][2]);
            acc[0][3] = fmaf(av.x, bv.w, acc[0][3]);
            acc[1][0] = fmaf(av.y, bv.x, acc[1][0]);
            acc[1][1] = fmaf(av.y, bv.y, acc[1][1]);
            acc[1][2] = fmaf(av.y, bv.z, acc[1][2]);
            acc[1][3] = fmaf(av.y, bv.w, acc[1][3]);
            acc[2][0] = fmaf(av.z, bv.x, acc[2][0]);
            acc[2][1] = fmaf(av.z, bv.y, acc[2][1]);
            acc[2][2] = fmaf(av.z, bv.z, acc[2][2]);
            acc[2][3] = fmaf(av.z, bv.w, acc[2][3]);
            acc[3][0] = fmaf(av.w, bv.x, acc[3][0]);
            acc[3][1] = fmaf(av.w, bv.y, acc[3][1]);
            acc[3][2] = fmaf(av.w, bv.z, acc[3][2]);
            acc[3][3] = fmaf(av.w, bv.w, acc[3][3]);
        }

        if (t + 1 < NT) {
            const int nxt = cur ^ 1;
            sm.As[nxt][lcol + 0][scol] = a0.x; sm.As[nxt][lcol + 1][scol] = a0.y;
            sm.As[nxt][lcol + 2][scol] = a0.z; sm.As[nxt][lcol + 3][scol] = a0.w;
            sm.As[nxt][lcol + 4][scol] = a1.x; sm.As[nxt][lcol + 5][scol] = a1.y;
            sm.As[nxt][lcol + 6][scol] = a1.z; sm.As[nxt][lcol + 7][scol] = a1.w;
            sm.Bs[nxt][lcol + 0][scol] = b0.x; sm.Bs[nxt][lcol + 1][scol] = b0.y;
            sm.Bs[nxt][lcol + 2][scol] = b0.z; sm.Bs[nxt][lcol + 3][scol] = b0.w;
            sm.Bs[nxt][lcol + 4][scol] = b1.x; sm.Bs[nxt][lcol + 5][scol] = b1.y;
            sm.Bs[nxt][lcol + 6][scol] = b1.z; sm.Bs[nxt][lcol + 7][scol] = b1.w;
        }
        __syncthreads();
    }

    // epilogue: float4 stores
    #pragma unroll
    for (int m = 0; m < 4; m++) {
        const int row = bm + ty * 4 + m;
        const int col = bn + tx * 4;
        float4 v = make_float4(acc[m][0], acc[m][1], acc[m][2], acc[m][3]);
        if (bias) {
            v.x += bias[col + 0]; v.y += bias[col + 1];
            v.z += bias[col + 2]; v.w += bias[col + 3];
        }
        *(float4*)&C[(size_t)row * N + col] = v;
    }
}

// Projections: z==0 -> q = query@Wq^T+bq ; z==1 -> k = key@Wk^T+bk
__global__ void __launch_bounds__(256) proj_kernel(
    const float* __restrict__ query, const float* __restrict__ key,
    const float* __restrict__ Wq, const float* __restrict__ bq,
    const float* __restrict__ Wk, const float* __restrict__ bk)
{
    __shared__ SmemTiles sm;
    const int bm = blockIdx.y * 64;
    const int bn = blockIdx.x * 64;
    if (blockIdx.z == 0) gemm_nt_64x64<H, H>(sm, query, Wq, bq, g_q, bm, bn, H - 1);
    else                 gemm_nt_64x64<H, H>(sm, key,  Wk, bk, g_k, bm, bn, H - 1);
}

// grid (12, 13): y<12 -> QK tile (x, y); y==12 -> T tile (M-tile = x)
__global__ void __launch_bounds__(256) qk_kernel(const float* __restrict__ rke)
{
    __shared__ SmemTiles sm;
    if (blockIdx.y < 12) {
        gemm_nt_64x64<S, H>(sm, g_q, g_k, nullptr, g_QK,
                            blockIdx.y * 64, blockIdx.x * 64, S - 1);
    } else {
        // g_T[768, 64] = q @ rel_k_emb^T  (cols >= R are garbage, never read)
        gemm_nt_64x64<TPAD, H>(sm, g_q, rke, nullptr, g_T,
                               blockIdx.x * 64, 0, R - 1);
    }
}

// ---------------------------------------------------------------------------
// out[i,j] = softmax_j( (QK[i,j] + T[i,rel[i,j]]) / 16, mask )
// One block of 192 threads per row; each thread owns one float4 (4 cols).
// ---------------------------------------------------------------------------
__global__ void __launch_bounds__(192) softmax_kernel(
    const int* __restrict__ rel, const int* __restrict__ mask,
    float* __restrict__ out)
{
    const int i = blockIdx.x;
    const int tid = threadIdx.x;
    const int lane = tid & 31;
    const int warp = tid >> 5;   // 0..5

    __shared__ float Trow[TPAD];
    __shared__ float redmx[6];
    __shared__ float redsm[6];

    if (tid < TPAD) Trow[tid] = g_T[(size_t)i * TPAD + tid];
    __syncthreads();

    const int4 r4 = *(const int4*)(rel  + (size_t)i * S + tid * 4);
    const int4 m4 = *(const int4*)(mask + (size_t)i * S + tid * 4);
    const float4 qk = *(const float4*)(g_QK + (size_t)i * S + tid * 4);

    float s0 = (m4.x == 0) ? -1e9f : (qk.x + Trow[r4.x]) * 0.0625f;
    float s1 = (m4.y == 0) ? -1e9f : (qk.y + Trow[r4.y]) * 0.0625f;
    float s2 = (m4.z == 0) ? -1e9f : (qk.z + Trow[r4.z]) * 0.0625f;
    float s3 = (m4.w == 0) ? -1e9f : (qk.w + Trow[r4.w]) * 0.0625f;

    float mx = fmaxf(fmaxf(s0, s1), fmaxf(s2, s3));
    #pragma unroll
    for (int o = 16; o > 0; o >>= 1) mx = fmaxf(mx, __shfl_xor_sync(0xffffffffu, mx, o));
    if (lane == 0) redmx[warp] = mx;
    __syncthreads();
    mx = redmx[0];
    #pragma unroll
    for (int w = 1; w < 6; w++) mx = fmaxf(mx, redmx[w]);

    s0 = __expf(s0 - mx); s1 = __expf(s1 - mx);
    s2 = __expf(s2 - mx); s3 = __expf(s3 - mx);
    float sum = (s0 + s1) + (s2 + s3);
    #pragma unroll
    for (int o = 16; o > 0; o >>= 1) sum += __shfl_xor_sync(0xffffffffu, sum, o);
    if (lane == 0) redsm[warp] = sum;
    __syncthreads();
    sum = redsm[0];
    #pragma unroll
    for (int w = 1; w < 6; w++) sum += redsm[w];

    const float inv = 1.0f / sum;
    float4 o4 = make_float4(s0 * inv, s1 * inv, s2 * inv, s3 * inv);
    *(float4*)(out + (size_t)i * S + tid * 4) = o4;
}

extern "C" void kernel_launch(void* const* d_in, const int* in_sizes, int n_in,
                              void* d_out, int out_size)
{
    // metadata order: query, key, value, relation, mask, Wq, bq, Wk, bk, Wv, bv,
    //                 rel_k_emb, rel_v_emb
    const float* query = (const float*)d_in[0];
    const float* key   = (const float*)d_in[1];
    const int*   rel   = (const int*)d_in[3];   // int32 (JAX x64 disabled)
    const int*   mask  = (const int*)d_in[4];
    const float* Wq    = (const float*)d_in[5];
    const float* bq    = (const float*)d_in[6];
    const float* Wk    = (const float*)d_in[7];
    const float* bk    = (const float*)d_in[8];
    const float* rke   = (const float*)d_in[11];
    float*       out   = (float*)d_out;

    dim3 gproj(H / 64, S / 64, 2);   // (4, 12, 2)
    proj_kernel<<<gproj, 256>>>(query, key, Wq, bq, Wk, bk);

    dim3 gqk(S / 64, S / 64 + 1, 1); // (12, 13): 144 QK tiles + 12 T tiles
    qk_kernel<<<gqk, 256>>>(rke);

    softmax_kernel<<<S, 192>>>(rel, mask, out);
}

// round 6
// speedup vs baseline: 2.2212x; 1.0607x over previous
#include <cuda_runtime.h>

#define S 768
#define H 256
#define R 51
#define TPAD 64   // padded relation-kind count for g_T

// Scratch (allocation-free rule: __device__ globals)
__device__ float g_q[S * H];
__device__ float g_k[S * H];
__device__ float g_QK[S * S];
__device__ float g_T[S * TPAD];

struct SmemTiles {
    float As[2][32][32];   // [buf][k][m]
    float Bs[2][32][64];   // [buf][k][n]
};

// ---------------------------------------------------------------------------
// Tiled fp32 GEMM: C[bm:bm+32, bn:bn+64] = A[32,K] @ B[64,K]^T (+ bias).
// 128 threads, 4x4 per thread, double-buffered XOR-swizzled smem.
// Element (k, col) lives at [k][col ^ (k & 24)] -> conflict-free transpose
// STS and conflict-free float4 LDS frag reads.
// b_row_max clamps B row index (for padded-N GEMMs reading a short B).
// ---------------------------------------------------------------------------
template<int N, int K>
__device__ __forceinline__ void gemm_nt_32x64(
    SmemTiles& sm,
    const float* __restrict__ A, const float* __restrict__ B,
    const float* __restrict__ bias, float* __restrict__ C,
    int bm, int bn, int b_row_max)
{
    const int tid = threadIdx.x;
    const int tx = tid & 15;   // n group (0..15)
    const int ty = tid >> 4;   // m group (0..7)

    const int lr = tid >> 2;            // 0..31
    const int lc = (tid & 3) * 8;       // 0,8,16,24 (k-offset of 8-float chunk)

    const float* pA = A + (size_t)(bm + lr) * K + lc;
    int br0 = bn + lr;      if (br0 > b_row_max) br0 = b_row_max;
    int br1 = bn + lr + 32; if (br1 > b_row_max) br1 = b_row_max;
    const float* pB0 = B + (size_t)br0 * K + lc;
    const float* pB1 = B + (size_t)br1 * K + lc;

    const int sca  = lr ^ lc;          // swizzled col for A rows / B rows 0..31
    const int scb1 = (lr + 32) ^ lc;   // swizzled col for B rows 32..63

    float acc[4][4] = {};
    float4 a0, a1, b0, b1, b2, b3;

#define STORE_TILE(buf)                                                      \
    do {                                                                     \
        sm.As[buf][lc+0][sca] = a0.x; sm.As[buf][lc+1][sca] = a0.y;          \
        sm.As[buf][lc+2][sca] = a0.z; sm.As[buf][lc+3][sca] = a0.w;          \
        sm.As[buf][lc+4][sca] = a1.x; sm.As[buf][lc+5][sca] = a1.y;          \
        sm.As[buf][lc+6][sca] = a1.z; sm.As[buf][lc+7][sca] = a1.w;          \
        sm.Bs[buf][lc+0][sca] = b0.x; sm.Bs[buf][lc+1][sca] = b0.y;          \
        sm.Bs[buf][lc+2][sca] = b0.z; sm.Bs[buf][lc+3][sca] = b0.w;          \
        sm.Bs[buf][lc+4][sca] = b1.x; sm.Bs[buf][lc+5][sca] = b1.y;          \
        sm.Bs[buf][lc+6][sca] = b1.z; sm.Bs[buf][lc+7][sca] = b1.w;          \
        sm.Bs[buf][lc+0][scb1] = b2.x; sm.Bs[buf][lc+1][scb1] = b2.y;        \
        sm.Bs[buf][lc+2][scb1] = b2.z; sm.Bs[buf][lc+3][scb1] = b2.w;        \
        sm.Bs[buf][lc+4][scb1] = b3.x; sm.Bs[buf][lc+5][scb1] = b3.y;        \
        sm.Bs[buf][lc+6][scb1] = b3.z; sm.Bs[buf][lc+7][scb1] = b3.w;        \
    } while (0)

    // prologue: tile 0
    a0 = *(const float4*)(pA);       a1 = *(const float4*)(pA + 4);
    b0 = *(const float4*)(pB0);      b1 = *(const float4*)(pB0 + 4);
    b2 = *(const float4*)(pB1);      b3 = *(const float4*)(pB1 + 4);
    STORE_TILE(0);
    __syncthreads();

    constexpr int NT = K / 32;
    #pragma unroll 1
    for (int t = 0; t < NT; t++) {
        const int cur = t & 1;
        if (t + 1 < NT) {
            const int off = (t + 1) * 32;
            a0 = *(const float4*)(pA  + off); a1 = *(const float4*)(pA  + off + 4);
            b0 = *(const float4*)(pB0 + off); b1 = *(const float4*)(pB0 + off + 4);
            b2 = *(const float4*)(pB1 + off); b3 = *(const float4*)(pB1 + off + 4);
        }

        #pragma unroll 16
        for (int kk = 0; kk < 32; kk++) {
            const int sw = kk & 24;
            float4 av = *(const float4*)&sm.As[cur][kk][(ty * 4) ^ sw];
            float4 bv = *(const float4*)&sm.Bs[cur][kk][(tx * 4) ^ sw];
            acc[0][0] = fmaf(av.x, bv.x, acc[0][0]);
            acc[0][1] = fmaf(av.x, bv.y, acc[0][1]);
            acc[0][2] = fmaf(av.x, bv.z, acc[0][2]);
            acc[0][3] = fmaf(av.x, bv.w, acc[0][3]);
            acc[1][0] = fmaf(av.y, bv.x, acc[1][0]);
            acc[1][1] = fmaf(av.y, bv.y, acc[1][1]);
            acc[1][2] = fmaf(av.y, bv.z, acc[1][2]);
            acc[1][3] = fmaf(av.y, bv.w, acc[1][3]);
            acc[2][0] = fmaf(av.z, bv.x, acc[2][0]);
            acc[2][1] = fmaf(av.z, bv.y, acc[2][1]);
            acc[2][2] = fmaf(av.z, bv.z, acc[2][2]);
            acc[2][3] = fmaf(av.z, bv.w, acc[2][3]);
            acc[3][0] = fmaf(av.w, bv.x, acc[3][0]);
            acc[3][1] = fmaf(av.w, bv.y, acc[3][1]);
            acc[3][2] = fmaf(av.w, bv.z, acc[3][2]);
            acc[3][3] = fmaf(av.w, bv.w, acc[3][3]);
        }

        if (t + 1 < NT) {
            const int nxt = cur ^ 1;
            STORE_TILE(nxt);
        }
        __syncthreads();
    }
#undef STORE_TILE

    // epilogue: float4 stores
    #pragma unroll
    for (int m = 0; m < 4; m++) {
        const int row = bm + ty * 4 + m;
        const int col = bn + tx * 4;
        float4 v = make_float4(acc[m][0], acc[m][1], acc[m][2], acc[m][3]);
        if (bias) {
            v.x += bias[col + 0]; v.y += bias[col + 1];
            v.z += bias[col + 2]; v.w += bias[col + 3];
        }
        *(float4*)&C[(size_t)row * N + col] = v;
    }
}

// Projections: z==0 -> q = query@Wq^T+bq ; z==1 -> k = key@Wk^T+bk
__global__ void __launch_bounds__(128) proj_kernel(
    const float* __restrict__ query, const float* __restrict__ key,
    const float* __restrict__ Wq, const float* __restrict__ bq,
    const float* __restrict__ Wk, const float* __restrict__ bk)
{
    __shared__ SmemTiles sm;
    const int bm = blockIdx.y * 32;
    const int bn = blockIdx.x * 64;
    if (blockIdx.z == 0) gemm_nt_32x64<H, H>(sm, query, Wq, bq, g_q, bm, bn, H - 1);
    else                 gemm_nt_32x64<H, H>(sm, key,  Wk, bk, g_k, bm, bn, H - 1);
}

// grid (12, 26): y<24 -> QK tile (bm=y*32, bn=x*64);
//                y>=24 -> T tile (bm = ((y-24)*12 + x)*32, bn=0)
__global__ void __launch_bounds__(128) qk_kernel(const float* __restrict__ rke)
{
    __shared__ SmemTiles sm;
    if (blockIdx.y < 24) {
        gemm_nt_32x64<S, H>(sm, g_q, g_k, nullptr, g_QK,
                            blockIdx.y * 32, blockIdx.x * 64, S - 1);
    } else {
        // g_T[768, 64] = q @ rel_k_emb^T  (cols >= R are garbage, never read)
        const int bm = ((blockIdx.y - 24) * 12 + blockIdx.x) * 32;
        gemm_nt_32x64<TPAD, H>(sm, g_q, rke, nullptr, g_T, bm, 0, R - 1);
    }
}

// ---------------------------------------------------------------------------
// out[i,j] = softmax_j( (QK[i,j] + T[i,rel[i,j]]) / 16, mask )
// One block of 192 threads per row; each thread owns one float4 (4 cols).
// ---------------------------------------------------------------------------
__global__ void __launch_bounds__(192) softmax_kernel(
    const int* __restrict__ rel, const int* __restrict__ mask,
    float* __restrict__ out)
{
    const int i = blockIdx.x;
    const int tid = threadIdx.x;
    const int lane = tid & 31;
    const int warp = tid >> 5;   // 0..5

    __shared__ float Trow[TPAD];
    __shared__ float redmx[6];
    __shared__ float redsm[6];

    if (tid < TPAD) Trow[tid] = g_T[(size_t)i * TPAD + tid];
    __syncthreads();

    const int4 r4 = *(const int4*)(rel  + (size_t)i * S + tid * 4);
    const int4 m4 = *(const int4*)(mask + (size_t)i * S + tid * 4);
    const float4 qk = *(const float4*)(g_QK + (size_t)i * S + tid * 4);

    float s0 = (m4.x == 0) ? -1e9f : (qk.x + Trow[r4.x]) * 0.0625f;
    float s1 = (m4.y == 0) ? -1e9f : (qk.y + Trow[r4.y]) * 0.0625f;
    float s2 = (m4.z == 0) ? -1e9f : (qk.z + Trow[r4.z]) * 0.0625f;
    float s3 = (m4.w == 0) ? -1e9f : (qk.w + Trow[r4.w]) * 0.0625f;

    float mx = fmaxf(fmaxf(s0, s1), fmaxf(s2, s3));
    #pragma unroll
    for (int o = 16; o > 0; o >>= 1) mx = fmaxf(mx, __shfl_xor_sync(0xffffffffu, mx, o));
    if (lane == 0) redmx[warp] = mx;
    __syncthreads();
    mx = redmx[0];
    #pragma unroll
    for (int w = 1; w < 6; w++) mx = fmaxf(mx, redmx[w]);

    s0 = __expf(s0 - mx); s1 = __expf(s1 - mx);
    s2 = __expf(s2 - mx); s3 = __expf(s3 - mx);
    float sum = (s0 + s1) + (s2 + s3);
    #pragma unroll
    for (int o = 16; o > 0; o >>= 1) sum += __shfl_xor_sync(0xffffffffu, sum, o);
    if (lane == 0) redsm[warp] = sum;
    __syncthreads();
    sum = redsm[0];
    #pragma unroll
    for (int w = 1; w < 6; w++) sum += redsm[w];

    const float inv = 1.0f / sum;
    float4 o4 = make_float4(s0 * inv, s1 * inv, s2 * inv, s3 * inv);
    *(float4*)(out + (size_t)i * S + tid * 4) = o4;
}

extern "C" void kernel_launch(void* const* d_in, const int* in_sizes, int n_in,
                              void* d_out, int out_size)
{
    // metadata order: query, key, value, relation, mask, Wq, bq, Wk, bk, Wv, bv,
    //                 rel_k_emb, rel_v_emb
    const float* query = (const float*)d_in[0];
    const float* key   = (const float*)d_in[1];
    const int*   rel   = (const int*)d_in[3];   // int32 (JAX x64 disabled)
    const int*   mask  = (const int*)d_in[4];
    const float* Wq    = (const float*)d_in[5];
    const float* bq    = (const float*)d_in[6];
    const float* Wk    = (const float*)d_in[7];
    const float* bk    = (const float*)d_in[8];
    const float* rke   = (const float*)d_in[11];
    float*       out   = (float*)d_out;

    dim3 gproj(H / 64, S / 32, 2);   // (4, 24, 2) = 192 blocks
    proj_kernel<<<gproj, 128>>>(query, key, Wq, bq, Wk, bk);

    dim3 gqk(S / 64, S / 32 + 2, 1); // (12, 26) = 288 QK + 24 T = 312 blocks
    qk_kernel<<<gqk, 128>>>(rke);

    softmax_kernel<<<S, 192>>>(rel, mask, out);
}

// round 7
// speedup vs baseline: 2.2948x; 1.0332x over previous
#include <cuda_runtime.h>

#define S 768
#define H 256
#define R 51
#define TPAD 64   // padded relation-kind count for g_T

// Scratch (allocation-free rule: __device__ globals)
// g_part[z]: z=0 q-half0(+bias), z=1 k-half0(+bias), z=2 q-half1, z=3 k-half1
__device__ float g_part[4][S * H];
__device__ float g_QK[S * S];
__device__ float g_T[S * TPAD];

struct SmemTiles {
    float As[2][32][32];   // [buf][k][m]
    float Bs[2][32][64];   // [buf][k][n]
};

__device__ __forceinline__ float4 f4add(float4 a, float4 b) {
    return make_float4(a.x + b.x, a.y + b.y, a.z + b.z, a.w + b.w);
}

// ---------------------------------------------------------------------------
// Shared MMA core: given filled smem tiles, accumulate 4x4 per thread.
// ---------------------------------------------------------------------------
__device__ __forceinline__ void mma_32x64(SmemTiles& sm, int cur,
                                          int ty, int tx, float acc[4][4])
{
    #pragma unroll 16
    for (int kk = 0; kk < 32; kk++) {
        const int sw = kk & 24;
        float4 av = *(const float4*)&sm.As[cur][kk][(ty * 4) ^ sw];
        float4 bv = *(const float4*)&sm.Bs[cur][kk][(tx * 4) ^ sw];
        acc[0][0] = fmaf(av.x, bv.x, acc[0][0]);
        acc[0][1] = fmaf(av.x, bv.y, acc[0][1]);
        acc[0][2] = fmaf(av.x, bv.z, acc[0][2]);
        acc[0][3] = fmaf(av.x, bv.w, acc[0][3]);
        acc[1][0] = fmaf(av.y, bv.x, acc[1][0]);
        acc[1][1] = fmaf(av.y, bv.y, acc[1][1]);
        acc[1][2] = fmaf(av.y, bv.z, acc[1][2]);
        acc[1][3] = fmaf(av.y, bv.w, acc[1][3]);
        acc[2][0] = fmaf(av.z, bv.x, acc[2][0]);
        acc[2][1] = fmaf(av.z, bv.y, acc[2][1]);
        acc[2][2] = fmaf(av.z, bv.z, acc[2][2]);
        acc[2][3] = fmaf(av.z, bv.w, acc[2][3]);
        acc[3][0] = fmaf(av.w, bv.x, acc[3][0]);
        acc[3][1] = fmaf(av.w, bv.y, acc[3][1]);
        acc[3][2] = fmaf(av.w, bv.z, acc[3][2]);
        acc[3][3] = fmaf(av.w, bv.w, acc[3][3]);
    }
}

__device__ __forceinline__ void epilogue_32x64(
    const float acc[4][4], const float* bias, float* C, int N,
    int bm, int bn, int ty, int tx)
{
    #pragma unroll
    for (int m = 0; m < 4; m++) {
        const int row = bm + ty * 4 + m;
        const int col = bn + tx * 4;
        float4 v = make_float4(acc[m][0], acc[m][1], acc[m][2], acc[m][3]);
        if (bias) {
            v.x += bias[col + 0]; v.y += bias[col + 1];
            v.z += bias[col + 2]; v.w += bias[col + 3];
        }
        *(float4*)&C[(size_t)row * N + col] = v;
    }
}

// ---------------------------------------------------------------------------
// proj: split-K GEMM. C[bm:+32, bn:+64] = A[:, k0:k0+128] @ B[:, k0:k0+128]^T
// (+ bias if half 0). 128 threads, NT=4, double-buffered swizzled smem.
// A rows stride 256 (=H). Single-source loads.
// ---------------------------------------------------------------------------
__global__ void __launch_bounds__(128) proj_kernel(
    const float* __restrict__ query, const float* __restrict__ key,
    const float* __restrict__ Wq, const float* __restrict__ bq,
    const float* __restrict__ Wk, const float* __restrict__ bk)
{
    __shared__ SmemTiles sm;

    const int z = blockIdx.z;             // 0..3
    const int half = z >> 1;              // k-half
    const int mat  = z & 1;               // 0=q, 1=k
    const int k0 = half * 128;
    const float* A = mat ? key : query;
    const float* B = mat ? Wk  : Wq;
    const float* bias = half ? nullptr : (mat ? bk : bq);
    float* C = g_part[z];

    const int bm = blockIdx.y * 32;
    const int bn = blockIdx.x * 64;

    const int tid = threadIdx.x;
    const int tx = tid & 15, ty = tid >> 4;
    const int lr = tid >> 2;            // 0..31
    const int lc = (tid & 3) * 8;       // 0,8,16,24

    const float* pA  = A + (size_t)(bm + lr) * H + k0 + lc;
    const float* pB0 = B + (size_t)(bn + lr) * H + k0 + lc;
    const float* pB1 = B + (size_t)(bn + lr + 32) * H + k0 + lc;

    const int sca  = lr ^ lc;
    const int scb1 = (lr + 32) ^ lc;

    float acc[4][4] = {};
    float4 a0, a1, b0, b1, b2, b3;

#define PSTORE(buf)                                                          \
    do {                                                                     \
        sm.As[buf][lc+0][sca] = a0.x; sm.As[buf][lc+1][sca] = a0.y;          \
        sm.As[buf][lc+2][sca] = a0.z; sm.As[buf][lc+3][sca] = a0.w;          \
        sm.As[buf][lc+4][sca] = a1.x; sm.As[buf][lc+5][sca] = a1.y;          \
        sm.As[buf][lc+6][sca] = a1.z; sm.As[buf][lc+7][sca] = a1.w;          \
        sm.Bs[buf][lc+0][sca] = b0.x; sm.Bs[buf][lc+1][sca] = b0.y;          \
        sm.Bs[buf][lc+2][sca] = b0.z; sm.Bs[buf][lc+3][sca] = b0.w;          \
        sm.Bs[buf][lc+4][sca] = b1.x; sm.Bs[buf][lc+5][sca] = b1.y;          \
        sm.Bs[buf][lc+6][sca] = b1.z; sm.Bs[buf][lc+7][sca] = b1.w;          \
        sm.Bs[buf][lc+0][scb1] = b2.x; sm.Bs[buf][lc+1][scb1] = b2.y;        \
        sm.Bs[buf][lc+2][scb1] = b2.z; sm.Bs[buf][lc+3][scb1] = b2.w;        \
        sm.Bs[buf][lc+4][scb1] = b3.x; sm.Bs[buf][lc+5][scb1] = b3.y;        \
        sm.Bs[buf][lc+6][scb1] = b3.z; sm.Bs[buf][lc+7][scb1] = b3.w;        \
    } while (0)

    a0 = *(const float4*)(pA);  a1 = *(const float4*)(pA + 4);
    b0 = *(const float4*)(pB0); b1 = *(const float4*)(pB0 + 4);
    b2 = *(const float4*)(pB1); b3 = *(const float4*)(pB1 + 4);
    PSTORE(0);
    __syncthreads();

    #pragma unroll 1
    for (int t = 0; t < 4; t++) {
        const int cur = t & 1;
        if (t + 1 < 4) {
            const int off = (t + 1) * 32;
            a0 = *(const float4*)(pA  + off); a1 = *(const float4*)(pA  + off + 4);
            b0 = *(const float4*)(pB0 + off); b1 = *(const float4*)(pB0 + off + 4);
            b2 = *(const float4*)(pB1 + off); b3 = *(const float4*)(pB1 + off + 4);
        }
        mma_32x64(sm, cur, ty, tx, acc);
        if (t + 1 < 4) PSTORE(cur ^ 1);
        __syncthreads();
    }
#undef PSTORE

    epilogue_32x64(acc, bias, C, H, bm, bn, ty, tx);
}

// ---------------------------------------------------------------------------
// qk: C = (A0+A1) @ (B0[+B1])^T. A is q (summed halves along K? No --
// halves are K-slices: full q row = concat? NO: partials are K-SPLIT SUMS.)
// g_part[z] are PARTIAL SUMS over K-halves: q = g_part[0] + g_part[2].
// Loader sums element-wise. B1 nullable (T tiles use raw rel_k_emb).
// 128 threads, K=256 (NT=8), 32x64 tiles.
// ---------------------------------------------------------------------------
__global__ void __launch_bounds__(128) qk_kernel(const float* __restrict__ rke)
{
    __shared__ SmemTiles sm;

    const float* A0 = g_part[0];
    const float* A1 = g_part[2];
    const float* B0;
    const float* B1;
    float* C;
    int bm, bn, Nout, b_row_max;

    if (blockIdx.y < 24) {
        B0 = g_part[1]; B1 = g_part[3];
        C = g_QK; Nout = S;
        bm = blockIdx.y * 32; bn = blockIdx.x * 64; b_row_max = S - 1;
    } else {
        B0 = rke; B1 = nullptr;
        C = g_T; Nout = TPAD;
        bm = ((blockIdx.y - 24) * 12 + blockIdx.x) * 32; bn = 0;
        b_row_max = R - 1;
    }

    const int tid = threadIdx.x;
    const int tx = tid & 15, ty = tid >> 4;
    const int lr = tid >> 2;
    const int lc = (tid & 3) * 8;

    const size_t aoff = (size_t)(bm + lr) * H + lc;
    int br0 = bn + lr;      if (br0 > b_row_max) br0 = b_row_max;
    int br1 = bn + lr + 32; if (br1 > b_row_max) br1 = b_row_max;
    const size_t boff0 = (size_t)br0 * H + lc;
    const size_t boff1 = (size_t)br1 * H + lc;

    const int sca  = lr ^ lc;
    const int scb1 = (lr + 32) ^ lc;

    float acc[4][4] = {};
    float4 a0, a1, b0, b1, b2, b3;

#define QLOAD(off)                                                            \
    do {                                                                      \
        a0 = f4add(*(const float4*)(A0 + aoff + (off)),                       \
                   *(const float4*)(A1 + aoff + (off)));                      \
        a1 = f4add(*(const float4*)(A0 + aoff + (off) + 4),                   \
                   *(const float4*)(A1 + aoff + (off) + 4));                  \
        b0 = *(const float4*)(B0 + boff0 + (off));                            \
        b1 = *(const float4*)(B0 + boff0 + (off) + 4);                        \
        b2 = *(const float4*)(B0 + boff1 + (off));                            \
        b3 = *(const float4*)(B0 + boff1 + (off) + 4);                        \
        if (B1) {                                                             \
            b0 = f4add(b0, *(const float4*)(B1 + boff0 + (off)));             \
            b1 = f4add(b1, *(const float4*)(B1 + boff0 + (off) + 4));         \
            b2 = f4add(b2, *(const float4*)(B1 + boff1 + (off)));             \
            b3 = f4add(b3, *(const float4*)(B1 + boff1 + (off) + 4));         \
        }                                                                     \
    } while (0)

#define QSTORE(buf)                                                          \
    do {                                                                     \
        sm.As[buf][lc+0][sca] = a0.x; sm.As[buf][lc+1][sca] = a0.y;          \
        sm.As[buf][lc+2][sca] = a0.z; sm.As[buf][lc+3][sca] = a0.w;          \
        sm.As[buf][lc+4][sca] = a1.x; sm.As[buf][lc+5][sca] = a1.y;          \
        sm.As[buf][lc+6][sca] = a1.z; sm.As[buf][lc+7][sca] = a1.w;          \
        sm.Bs[buf][lc+0][sca] = b0.x; sm.Bs[buf][lc+1][sca] = b0.y;          \
        sm.Bs[buf][lc+2][sca] = b0.z; sm.Bs[buf][lc+3][sca] = b0.w;          \
        sm.Bs[buf][lc+4][sca] = b1.x; sm.Bs[buf][lc+5][sca] = b1.y;          \
        sm.Bs[buf][lc+6][sca] = b1.z; sm.Bs[buf][lc+7][sca] = b1.w;          \
        sm.Bs[buf][lc+0][scb1] = b2.x; sm.Bs[buf][lc+1][scb1] = b2.y;        \
        sm.Bs[buf][lc+2][scb1] = b2.z; sm.Bs[buf][lc+3][scb1] = b2.w;        \
        sm.Bs[buf][lc+4][scb1] = b3.x; sm.Bs[buf][lc+5][scb1] = b3.y;        \
        sm.Bs[buf][lc+6][scb1] = b3.z; sm.Bs[buf][lc+7][scb1] = b3.w;        \
    } while (0)

    QLOAD(0);
    QSTORE(0);
    __syncthreads();

    #pragma unroll 1
    for (int t = 0; t < 8; t++) {
        const int cur = t & 1;
        if (t + 1 < 8) QLOAD((t + 1) * 32);
        mma_32x64(sm, cur, ty, tx, acc);
        if (t + 1 < 8) QSTORE(cur ^ 1);
        __syncthreads();
    }
#undef QLOAD
#undef QSTORE

    epilogue_32x64(acc, nullptr, C, Nout, bm, bn, ty, tx);
}

// ---------------------------------------------------------------------------
// out[i,j] = softmax_j( (QK[i,j] + T[i,rel[i,j]]) / 16, mask )
// One block of 192 threads per row; each thread owns one float4 (4 cols).
// ---------------------------------------------------------------------------
__global__ void __launch_bounds__(192) softmax_kernel(
    const int* __restrict__ rel, const int* __restrict__ mask,
    float* __restrict__ out)
{
    const int i = blockIdx.x;
    const int tid = threadIdx.x;
    const int lane = tid & 31;
    const int warp = tid >> 5;   // 0..5

    __shared__ float Trow[TPAD];
    __shared__ float redmx[6];
    __shared__ float redsm[6];

    if (tid < TPAD) Trow[tid] = g_T[(size_t)i * TPAD + tid];
    __syncthreads();

    const int4 r4 = *(const int4*)(rel  + (size_t)i * S + tid * 4);
    const int4 m4 = *(const int4*)(mask + (size_t)i * S + tid * 4);
    const float4 qk = *(const float4*)(g_QK + (size_t)i * S + tid * 4);

    float s0 = (m4.x == 0) ? -1e9f : (qk.x + Trow[r4.x]) * 0.0625f;
    float s1 = (m4.y == 0) ? -1e9f : (qk.y + Trow[r4.y]) * 0.0625f;
    float s2 = (m4.z == 0) ? -1e9f : (qk.z + Trow[r4.z]) * 0.0625f;
    float s3 = (m4.w == 0) ? -1e9f : (qk.w + Trow[r4.w]) * 0.0625f;

    float mx = fmaxf(fmaxf(s0, s1), fmaxf(s2, s3));
    #pragma unroll
    for (int o = 16; o > 0; o >>= 1) mx = fmaxf(mx, __shfl_xor_sync(0xffffffffu, mx, o));
    if (lane == 0) redmx[warp] = mx;
    __syncthreads();
    mx = redmx[0];
    #pragma unroll
    for (int w = 1; w < 6; w++) mx = fmaxf(mx, redmx[w]);

    s0 = __expf(s0 - mx); s1 = __expf(s1 - mx);
    s2 = __expf(s2 - mx); s3 = __expf(s3 - mx);
    float sum = (s0 + s1) + (s2 + s3);
    #pragma unroll
    for (int o = 16; o > 0; o >>= 1) sum += __shfl_xor_sync(0xffffffffu, sum, o);
    if (lane == 0) redsm[warp] = sum;
    __syncthreads();
    sum = redsm[0];
    #pragma unroll
    for (int w = 1; w < 6; w++) sum += redsm[w];

    const float inv = 1.0f / sum;
    float4 o4 = make_float4(s0 * inv, s1 * inv, s2 * inv, s3 * inv);
    *(float4*)(out + (size_t)i * S + tid * 4) = o4;
}

extern "C" void kernel_launch(void* const* d_in, const int* in_sizes, int n_in,
                              void* d_out, int out_size)
{
    // metadata order: query, key, value, relation, mask, Wq, bq, Wk, bk, Wv, bv,
    //                 rel_k_emb, rel_v_emb
    const float* query = (const float*)d_in[0];
    const float* key   = (const float*)d_in[1];
    const int*   rel   = (const int*)d_in[3];   // int32 (JAX x64 disabled)
    const int*   mask  = (const int*)d_in[4];
    const float* Wq    = (const float*)d_in[5];
    const float* bq    = (const float*)d_in[6];
    const float* Wk    = (const float*)d_in[7];
    const float* bk    = (const float*)d_in[8];
    const float* rke   = (const float*)d_in[11];
    float*       out   = (float*)d_out;

    dim3 gproj(H / 64, S / 32, 4);   // (4, 24, 4) = 384 split-K blocks
    proj_kernel<<<gproj, 128>>>(query, key, Wq, bq, Wk, bk);

    dim3 gqk(S / 64, S / 32 + 2, 1); // (12, 26) = 288 QK + 24 T = 312 blocks
    qk_kernel<<<gqk, 128>>>(rke);

    softmax_kernel<<<S, 192>>>(rel, mask, out);
}

// round 9
// speedup vs baseline: 2.3757x; 1.0353x over previous
#include <cuda_runtime.h>
#include <cstdint>

#define S 768
#define H 256
#define R 51
#define TPAD 64

// ---------------- scratch (__device__ globals; no allocation) ----------------
// proj partials: z = slice*2 + mat (mat 0=q, 1=k), slice 0..3 (K quarter)
__device__ float g_part[8][S * H];
__device__ float g_q[S * H];
__device__ float g_k[S * H];
__device__ float g_QKp[2][S * S];
__device__ float g_T[S * TPAD];

// ---------------- SIMT tile machinery ----------------
struct SmemTiles {
    float As[2][32][32];   // [buf][k][m]
    float Bs[2][32][64];   // [buf][k][n]
};

__device__ __forceinline__ void mma_32x64(SmemTiles& sm, int cur,
                                          int ty, int tx, float acc[4][4])
{
    #pragma unroll 16
    for (int kk = 0; kk < 32; kk++) {
        const int sw = kk & 24;
        float4 av = *(const float4*)&sm.As[cur][kk][(ty * 4) ^ sw];
        float4 bv = *(const float4*)&sm.Bs[cur][kk][(tx * 4) ^ sw];
        acc[0][0] = fmaf(av.x, bv.x, acc[0][0]);
        acc[0][1] = fmaf(av.x, bv.y, acc[0][1]);
        acc[0][2] = fmaf(av.x, bv.z, acc[0][2]);
        acc[0][3] = fmaf(av.x, bv.w, acc[0][3]);
        acc[1][0] = fmaf(av.y, bv.x, acc[1][0]);
        acc[1][1] = fmaf(av.y, bv.y, acc[1][1]);
        acc[1][2] = fmaf(av.y, bv.z, acc[1][2]);
        acc[1][3] = fmaf(av.y, bv.w, acc[1][3]);
        acc[2][0] = fmaf(av.z, bv.x, acc[2][0]);
        acc[2][1] = fmaf(av.z, bv.y, acc[2][1]);
        acc[2][2] = fmaf(av.z, bv.z, acc[2][2]);
        acc[2][3] = fmaf(av.z, bv.w, acc[2][3]);
        acc[3][0] = fmaf(av.w, bv.x, acc[3][0]);
        acc[3][1] = fmaf(av.w, bv.y, acc[3][1]);
        acc[3][2] = fmaf(av.w, bv.z, acc[3][2]);
        acc[3][3] = fmaf(av.w, bv.w, acc[3][3]);
    }
}

#define TILE_STORE(sm, buf)                                                  \
    do {                                                                     \
        sm.As[buf][lc+0][sca] = a0.x; sm.As[buf][lc+1][sca] = a0.y;          \
        sm.As[buf][lc+2][sca] = a0.z; sm.As[buf][lc+3][sca] = a0.w;          \
        sm.As[buf][lc+4][sca] = a1.x; sm.As[buf][lc+5][sca] = a1.y;          \
        sm.As[buf][lc+6][sca] = a1.z; sm.As[buf][lc+7][sca] = a1.w;          \
        sm.Bs[buf][lc+0][sca] = b0.x; sm.Bs[buf][lc+1][sca] = b0.y;          \
        sm.Bs[buf][lc+2][sca] = b0.z; sm.Bs[buf][lc+3][sca] = b0.w;          \
        sm.Bs[buf][lc+4][sca] = b1.x; sm.Bs[buf][lc+5][sca] = b1.y;          \
        sm.Bs[buf][lc+6][sca] = b1.z; sm.Bs[buf][lc+7][sca] = b1.w;          \
        sm.Bs[buf][lc+0][scb1] = b2.x; sm.Bs[buf][lc+1][scb1] = b2.y;        \
        sm.Bs[buf][lc+2][scb1] = b2.z; sm.Bs[buf][lc+3][scb1] = b2.w;        \
        sm.Bs[buf][lc+4][scb1] = b3.x; sm.Bs[buf][lc+5][scb1] = b3.y;        \
        sm.Bs[buf][lc+6][scb1] = b3.z; sm.Bs[buf][lc+7][scb1] = b3.w;        \
    } while (0)

#define TILE_LOAD(off)                                                        \
    do {                                                                      \
        a0 = *(const float4*)(pA  + (off)); a1 = *(const float4*)(pA  + (off) + 4); \
        b0 = *(const float4*)(pB0 + (off)); b1 = *(const float4*)(pB0 + (off) + 4); \
        b2 = *(const float4*)(pB1 + (off)); b3 = *(const float4*)(pB1 + (off) + 4); \
    } while (0)

// ---------------------------------------------------------------------------
// proj: split-K4. C[bm:+32, bn:+64] = A[:, k0:k0+64] @ B[:, k0:k0+64]^T
// (+ bias if slice 0). grid (4, 24, 8) = 768 blocks, NT=2.
// ---------------------------------------------------------------------------
__global__ void __launch_bounds__(128) proj_kernel(
    const float* __restrict__ query, const float* __restrict__ key,
    const float* __restrict__ Wq, const float* __restrict__ bq,
    const float* __restrict__ Wk, const float* __restrict__ bk)
{
    __shared__ SmemTiles sm;

    const int z = blockIdx.z;             // 0..7
    const int slice = z >> 1;             // K quarter
    const int mat   = z & 1;              // 0=q, 1=k
    const int k0 = slice * 64;
    const float* A = mat ? key : query;
    const float* B = mat ? Wk  : Wq;
    const float* bias = (slice == 0) ? (mat ? bk : bq) : nullptr;
    float* C = g_part[z];

    const int bm = blockIdx.y * 32;
    const int bn = blockIdx.x * 64;
    const int tid = threadIdx.x;
    const int tx = tid & 15, ty = tid >> 4;
    const int lr = tid >> 2;
    const int lc = (tid & 3) * 8;

    const float* pA  = A + (size_t)(bm + lr) * H + k0 + lc;
    const float* pB0 = B + (size_t)(bn + lr) * H + k0 + lc;
    const float* pB1 = B + (size_t)(bn + lr + 32) * H + k0 + lc;

    const int sca  = lr ^ lc;
    const int scb1 = (lr + 32) ^ lc;

    float acc[4][4] = {};
    float4 a0, a1, b0, b1, b2, b3;

    TILE_LOAD(0);
    TILE_STORE(sm, 0);
    __syncthreads();

    // t = 0
    TILE_LOAD(32);
    mma_32x64(sm, 0, ty, tx, acc);
    TILE_STORE(sm, 1);
    __syncthreads();
    // t = 1
    mma_32x64(sm, 1, ty, tx, acc);

    #pragma unroll
    for (int m = 0; m < 4; m++) {
        const int row = bm + ty * 4 + m;
        const int col = bn + tx * 4;
        float4 v = make_float4(acc[m][0], acc[m][1], acc[m][2], acc[m][3]);
        if (bias) {
            v.x += bias[col + 0]; v.y += bias[col + 1];
            v.z += bias[col + 2]; v.w += bias[col + 3];
        }
        *(float4*)&C[(size_t)row * H + col] = v;
    }
}

// ---------------- reduce: g_q / g_k = sum of 4 K-slice partials ----------------
__global__ void __launch_bounds__(256) reduce_kernel()
{
    const int idx = blockIdx.x * 256 + threadIdx.x;   // float4 index
    const int mat = blockIdx.y;                       // 0=q, 1=k
    float4 v0 = ((const float4*)g_part[0 + mat])[idx];
    float4 v1 = ((const float4*)g_part[2 + mat])[idx];
    float4 v2 = ((const float4*)g_part[4 + mat])[idx];
    float4 v3 = ((const float4*)g_part[6 + mat])[idx];
    float4 v = make_float4((v0.x + v1.x) + (v2.x + v3.x),
                           (v0.y + v1.y) + (v2.y + v3.y),
                           (v0.z + v1.z) + (v2.z + v3.z),
                           (v0.w + v1.w) + (v2.w + v3.w));
    ((float4*)(mat ? g_k : g_q))[idx] = v;
}

// ---------------------------------------------------------------------------
// qk: split-K2 QK tiles + full-K T tiles.
// grid (12, 50): y<48 -> QK: half h=y/24, bm=(y%24)*32, bn=x*64, K=128 -> g_QKp[h]
//                y>=48 -> T: bm=((y-48)*12+x)*32, full K=256 -> g_T
// ---------------------------------------------------------------------------
__global__ void __launch_bounds__(128) qk_kernel(const float* __restrict__ rke)
{
    __shared__ SmemTiles sm;

    const int tid = threadIdx.x;
    const int tx = tid & 15, ty = tid >> 4;
    const int lr = tid >> 2;
    const int lc = (tid & 3) * 8;

    const float* pA;
    const float* pB0;
    const float* pB1;
    float* C;
    int bm, bn, Nout, NT;

    if (blockIdx.y < 48) {
        const int h = blockIdx.y / 24;
        const int k0 = h * 128;
        bm = (blockIdx.y % 24) * 32;
        bn = blockIdx.x * 64;
        pA  = g_q + (size_t)(bm + lr) * H + k0 + lc;
        pB0 = g_k + (size_t)(bn + lr) * H + k0 + lc;
        pB1 = g_k + (size_t)(bn + lr + 32) * H + k0 + lc;
        C = g_QKp[h]; Nout = S; NT = 4;
    } else {
        bm = ((blockIdx.y - 48) * 12 + blockIdx.x) * 32;
        bn = 0;
        int br0 = lr;      if (br0 > R - 1) br0 = R - 1;
        int br1 = lr + 32; if (br1 > R - 1) br1 = R - 1;
        pA  = g_q + (size_t)(bm + lr) * H + lc;
        pB0 = rke + (size_t)br0 * H + lc;
        pB1 = rke + (size_t)br1 * H + lc;
        C = g_T; Nout = TPAD; NT = 8;
    }

    const int sca  = lr ^ lc;
    const int scb1 = (lr + 32) ^ lc;

    float acc[4][4] = {};
    float4 a0, a1, b0, b1, b2, b3;

    TILE_LOAD(0);
    TILE_STORE(sm, 0);
    __syncthreads();

    #pragma unroll 1
    for (int t = 0; t < NT; t++) {
        const int cur = t & 1;
        if (t + 1 < NT) TILE_LOAD((t + 1) * 32);
        mma_32x64(sm, cur, ty, tx, acc);
        if (t + 1 < NT) { const int nxt = cur ^ 1; TILE_STORE(sm, nxt); }
        __syncthreads();
    }

    #pragma unroll
    for (int m = 0; m < 4; m++) {
        const int row = bm + ty * 4 + m;
        const int col = bn + tx * 4;
        *(float4*)&C[(size_t)row * Nout + col] =
            make_float4(acc[m][0], acc[m][1], acc[m][2], acc[m][3]);
    }
}

// ---------------------------------------------------------------------------
// out[i,j] = softmax_j( (QKp0[i,j]+QKp1[i,j] + T[i,rel[i,j]]) / 16, mask )
// 192 threads per row, one float4 per thread.
// ---------------------------------------------------------------------------
__global__ void __launch_bounds__(192) softmax_kernel(
    const int* __restrict__ rel, const int* __restrict__ mask,
    float* __restrict__ out)
{
    const int i = blockIdx.x;
    const int tid = threadIdx.x;
    const int lane = tid & 31;
    const int warp = tid >> 5;

    __shared__ float Trow[TPAD];
    __shared__ float redmx[6];
    __shared__ float redsm[6];

    if (tid < TPAD) Trow[tid] = g_T[(size_t)i * TPAD + tid];
    __syncthreads();

    const size_t base = (size_t)i * S + tid * 4;
    const int4 r4 = *(const int4*)(rel  + base);
    const int4 m4 = *(const int4*)(mask + base);
    const float4 qa = *(const float4*)(g_QKp[0] + base);
    const float4 qb = *(const float4*)(g_QKp[1] + base);

    float s0 = (m4.x == 0) ? -1e9f : (qa.x + qb.x + Trow[r4.x]) * 0.0625f;
    float s1 = (m4.y == 0) ? -1e9f : (qa.y + qb.y + Trow[r4.y]) * 0.0625f;
    float s2 = (m4.z == 0) ? -1e9f : (qa.z + qb.z + Trow[r4.z]) * 0.0625f;
    float s3 = (m4.w == 0) ? -1e9f : (qa.w + qb.w + Trow[r4.w]) * 0.0625f;

    float mx = fmaxf(fmaxf(s0, s1), fmaxf(s2, s3));
    #pragma unroll
    for (int o = 16; o > 0; o >>= 1) mx = fmaxf(mx, __shfl_xor_sync(0xffffffffu, mx, o));
    if (lane == 0) redmx[warp] = mx;
    __syncthreads();
    mx = redmx[0];
    #pragma unroll
    for (int w = 1; w < 6; w++) mx = fmaxf(mx, redmx[w]);

    s0 = __expf(s0 - mx); s1 = __expf(s1 - mx);
    s2 = __expf(s2 - mx); s3 = __expf(s3 - mx);
    float sum = (s0 + s1) + (s2 + s3);
    #pragma unroll
    for (int o = 16; o > 0; o >>= 1) sum += __shfl_xor_sync(0xffffffffu, sum, o);
    if (lane == 0) redsm[warp] = sum;
    __syncthreads();
    sum = redsm[0];
    #pragma unroll
    for (int w = 1; w < 6; w++) sum += redsm[w];

    const float inv = 1.0f / sum;
    *(float4*)(out + base) = make_float4(s0 * inv, s1 * inv, s2 * inv, s3 * inv);
}

extern "C" void kernel_launch(void* const* d_in, const int* in_sizes, int n_in,
                              void* d_out, int out_size)
{
    const float* query = (const float*)d_in[0];
    const float* key   = (const float*)d_in[1];
    const int*   rel   = (const int*)d_in[3];
    const int*   mask  = (const int*)d_in[4];
    const float* Wq    = (const float*)d_in[5];
    const float* bq    = (const float*)d_in[6];
    const float* Wk    = (const float*)d_in[7];
    const float* bk    = (const float*)d_in[8];
    const float* rke   = (const float*)d_in[11];
    float*       out   = (float*)d_out;

    dim3 gproj(H / 64, S / 32, 8);           // 768 blocks
    proj_kernel<<<gproj, 128>>>(query, key, Wq, bq, Wk, bk);

    reduce_kernel<<<dim3(S * H / 4 / 256, 2), 256>>>();

    dim3 gqk(12, 50);                        // 576 QK + 24 T blocks
    qk_kernel<<<gqk, 128>>>(rke);

    softmax_kernel<<<S, 192>>>(rel, mask, out);
}